// round 13
// baseline (speedup 1.0000x reference)
#include <cuda_runtime.h>
#include <cuda_bf16.h>
#include <cstdint>

// ---------------- problem constants ----------------
#define BQ    256
#define NM    500000
#define DIM   512
#define KSEL  5
#define KCAND 16

// ---------------- GEMM tiling (int8) ----------------
#define MT      128                 // memory rows per CTA
#define NQT     128                 // queries per CTA
#define KC      128                 // s8 elems per chunk = 128B rows
#define GT      256                 // threads per CTA
#define NCHUNK  (DIM / KC)          // 4
#define NTILES  ((NM + MT - 1) / MT)        // 3907
#define NMP     (NTILES * MT)
#define NSTAGE  3
#define STAGE_B 32768               // A 16KB + B 16KB
#define SMEM_REQ (NSTAGE * STAGE_B + 1024)

// ---------------- int8 quantization ----------------
#define QS      19.5f               // scale: 127 / 6.5 (inputs ~N(0,1))
#define INV2S2  (2.0f / (QS * QS))  // dot = acc/S^2 ; d2 = qs+ms-2*dot

// ---------------- candidate filtering ----------------
#define SEEDN   1024
#define NBOUND  5                   // bound = exact 5th-smallest of seed set
#define CAP     24576
#define MARGIN  20.0f               // ~21 sigma of int8 quantization error

// ---------------- device scratch ----------------
__device__ float    g_msq[NMP];
__device__ float    g_qsq[BQ];
__device__ int8_t   g_mh[(size_t)NMP * DIM];
__device__ int8_t   g_qh[BQ * DIM];
__device__ float    g_bound[BQ];
__device__ unsigned g_ccnt[BQ];
__device__ float    g_cd[(size_t)BQ * CAP];
__device__ int      g_ci[(size_t)BQ * CAP];

// ---------------- helpers ----------------
__device__ __forceinline__ uint32_t smem_u32(const void* p) {
    uint32_t a;
    asm("{ .reg .u64 t; cvta.to.shared.u64 t, %1; cvt.u32.u64 %0, t; }" : "=r"(a) : "l"(p));
    return a;
}
#define SWZ(o) ((o) ^ (((o) >> 3) & 0x70))
#define CP16(dst, src) \
    asm volatile("cp.async.cg.shared.global [%0], [%1], 16;" :: "r"(dst), "l"(src))
#define LDSM4(r, addr)                                                    \
    asm volatile("ldmatrix.sync.aligned.m8n8.x4.shared.b16 {%0,%1,%2,%3}, [%4];" \
                 : "=r"((r)[0]), "=r"((r)[1]), "=r"((r)[2]), "=r"((r)[3]) \
                 : "r"(addr))
// int8 MMA, K=32 per instruction, exact s32 accumulation
#define MMAI8(d, a, b0, b1)                                               \
    asm volatile("mma.sync.aligned.m16n8k32.row.col.s32.s8.s8.s32 "       \
                 "{%0,%1,%2,%3}, {%4,%5,%6,%7}, {%8,%9}, {%0,%1,%2,%3};"  \
                 : "+r"((d)[0]), "+r"((d)[1]), "+r"((d)[2]), "+r"((d)[3]) \
                 : "r"((a)[0]), "r"((a)[1]), "r"((a)[2]), "r"((a)[3]),    \
                   "r"(b0), "r"(b1))

__device__ __forceinline__ int qz(float x) {
    return __float2int_rn(fminf(fmaxf(x * QS, -127.f), 127.f));
}
__device__ __forceinline__ uint32_t pack4(float4 v) {
    int a = qz(v.x), b = qz(v.y), c = qz(v.z), d = qz(v.w);
    return (uint32_t)(a & 0xff) | ((uint32_t)(b & 0xff) << 8) |
           ((uint32_t)(c & 0xff) << 16) | ((uint32_t)(d & 0xff) << 24);
}

// ---------------- s8 convert + exact squared-norm (one warp per row) ----------------
__global__ void split_kernel(const float* __restrict__ x,
                             int8_t* __restrict__ hi,
                             float* __restrict__ sq, int rows) {
    int warp = (blockIdx.x * blockDim.x + threadIdx.x) >> 5;
    int lane = threadIdx.x & 31;
    if (warp >= rows) return;
    const float4* r = (const float4*)(x + (size_t)warp * DIM);
    float s = 0.f;
    uint4 o;
    float4 v0 = r[lane * 4 + 0];
    float4 v1 = r[lane * 4 + 1];
    float4 v2 = r[lane * 4 + 2];
    float4 v3 = r[lane * 4 + 3];
    s += v0.x * v0.x + v0.y * v0.y + v0.z * v0.z + v0.w * v0.w;
    s += v1.x * v1.x + v1.y * v1.y + v1.z * v1.z + v1.w * v1.w;
    s += v2.x * v2.x + v2.y * v2.y + v2.z * v2.z + v2.w * v2.w;
    s += v3.x * v3.x + v3.y * v3.y + v3.z * v3.z + v3.w * v3.w;
    o.x = pack4(v0); o.y = pack4(v1); o.z = pack4(v2); o.w = pack4(v3);
    *(uint4*)(hi + (size_t)warp * DIM + lane * 16) = o;
    #pragma unroll
    for (int of = 16; of; of >>= 1) s += __shfl_xor_sync(0xffffffff, s, of);
    if (lane == 0) sq[warp] = s;
}

// ---------------- seed: exact fp32, bound[q] = 5th-smallest of first SEEDN rows + margin ----------------
__global__ __launch_bounds__(256)
void seed_kernel(const float* __restrict__ query, const float* __restrict__ memory) {
    const int q = blockIdx.x;
    const int tid = threadIdx.x;
    __shared__ float4 qs[DIM / 4];
    __shared__ float sd[SEEDN];
    __shared__ float rv[256];
    __shared__ int   ri[256];

    if (tid == 0) g_ccnt[q] = 0;   // zero candidate counter (replaces memset)

    for (int i = tid; i < DIM / 4; i += 256)
        qs[i] = ((const float4*)(query + (size_t)q * DIM))[i];
    __syncthreads();

    for (int r = tid; r < SEEDN; r += 256) {
        const float4* m4 = (const float4*)(memory + (size_t)r * DIM);
        float d = 0.f;
        #pragma unroll 8
        for (int i = 0; i < DIM / 4; i++) {
            float4 a = qs[i], b = m4[i];
            float dx = a.x - b.x, dy = a.y - b.y, dz = a.z - b.z, dw = a.w - b.w;
            d += dx * dx + dy * dy + dz * dz + dw * dw;
        }
        sd[r] = d;
    }
    __syncthreads();

    float last = 0.f;
    for (int sel = 0; sel < NBOUND; sel++) {
        float bv = 3.4e38f; int bi = -1;
        #pragma unroll
        for (int k = 0; k < SEEDN / 256; k++) {
            int i = tid + k * 256;
            float v = sd[i];
            if (v < bv) { bv = v; bi = i; }
        }
        rv[tid] = bv; ri[tid] = bi;
        __syncthreads();
        for (int s = 128; s > 0; s >>= 1) {
            if (tid < s) {
                if (rv[tid + s] < rv[tid]) { rv[tid] = rv[tid + s]; ri[tid] = ri[tid + s]; }
            }
            __syncthreads();
        }
        if (tid == 0) { last = rv[0]; sd[ri[0]] = 3.4e38f; }
        __syncthreads();
    }
    if (tid == 0) g_bound[q] = last + MARGIN;
}

// ---------------- int8 MMA GEMM with fused candidate push ----------------
// CTA: 128 rows x 128 queries, 256 threads, 8 warps (wm 2 x wn 4), warp 64x32.
__global__ __launch_bounds__(GT, 2)
void gemm_kernel() {
    extern __shared__ char dsm[];
    __shared__ float s_qsq[NQT];
    __shared__ float s_bnd[NQT];
    char* alig = (char*)(((uintptr_t)dsm + 1023) & ~(uintptr_t)1023);
    const uint32_t base = smem_u32(alig);

    const int tid  = threadIdx.x;
    const int wid  = tid >> 5;
    const int lane = tid & 31;
    const int wm   = wid >> 2;
    const int wn   = wid & 3;
    const size_t n0 = (size_t)blockIdx.y * MT;   // y = row tile
    const int q0g   = blockIdx.x * NQT;          // x = query half (adjacent bids share A in L2)

    if (tid < NQT) { s_qsq[tid] = g_qsq[q0g + tid]; s_bnd[tid] = g_bound[q0g + tid]; }

    int acc[4][4][4];
    #pragma unroll
    for (int mt = 0; mt < 4; mt++)
        #pragma unroll
        for (int j = 0; j < 4; j++)
            #pragma unroll
            for (int e = 0; e < 4; e++) acc[mt][j][e] = 0;

    auto load_stage = [&](int kc, int s) {
        const uint32_t aB = base + s * STAGE_B;
        const uint32_t bB = aB + 16384;
        #pragma unroll
        for (int i = 0; i < 4; i++) {           // A: 128 rows x 8 pieces of 16B
            int c = tid + i * GT;
            int row = c >> 3, piece = c & 7;
            const char* src = (const char*)g_mh +
                (n0 + (size_t)row) * DIM + (size_t)kc * KC + piece * 16;
            CP16(aB + SWZ(row * 128 + piece * 16), src);
        }
        #pragma unroll
        for (int i = 0; i < 4; i++) {           // B: 128 rows x 8 pieces of 16B
            int c = tid + i * GT;
            int row = c >> 3, piece = c & 7;
            const char* src = (const char*)g_qh +
                (size_t)(q0g + row) * DIM + (size_t)kc * KC + piece * 16;
            CP16(bB + SWZ(row * 128 + piece * 16), src);
        }
        asm volatile("cp.async.commit_group;" ::: "memory");
    };

    load_stage(0, 0);
    load_stage(1, 1);

    const int arow  = (lane & 15);
    const int ahalf = (lane >> 4) * 16;

    #pragma unroll 1
    for (int kc = 0; kc < NCHUNK; kc++) {
        const int s = kc % NSTAGE;
        if (kc + 2 < NCHUNK) {
            asm volatile("cp.async.wait_group 1;" ::: "memory");
        } else {
            asm volatile("cp.async.wait_group 0;" ::: "memory");
        }
        __syncthreads();
        if (kc + 2 < NCHUNK) load_stage(kc + 2, (kc + 2) % NSTAGE);

        const uint32_t aS = base + s * STAGE_B;
        const uint32_t bS = aS + 16384;

        uint32_t af[2][4][4], bf[2][2][4];
        #pragma unroll
        for (int mt = 0; mt < 4; mt++) {
            int row = wm * 64 + mt * 16 + arow;
            LDSM4(af[0][mt], aS + SWZ(row * 128 + ahalf));
        }
        #pragma unroll
        for (int nt = 0; nt < 2; nt++) {
            int row = wn * 32 + nt * 16 + arow;
            LDSM4(bf[0][nt], bS + SWZ(row * 128 + ahalf));
        }

        #pragma unroll
        for (int kk = 0; kk < 4; kk++) {        // 4 x k32 = 128
            const int cur = kk & 1;
            const int nxt = cur ^ 1;
            if (kk < 3) {
                #pragma unroll
                for (int mt = 0; mt < 4; mt++) {
                    int row = wm * 64 + mt * 16 + arow;
                    LDSM4(af[nxt][mt], aS + SWZ(row * 128 + (kk + 1) * 32 + ahalf));
                }
                #pragma unroll
                for (int nt = 0; nt < 2; nt++) {
                    int row = wn * 32 + nt * 16 + arow;
                    LDSM4(bf[nxt][nt], bS + SWZ(row * 128 + (kk + 1) * 32 + ahalf));
                }
            }
            #pragma unroll
            for (int mt = 0; mt < 4; mt++)
                #pragma unroll
                for (int j = 0; j < 4; j++)
                    MMAI8(acc[mt][j], af[cur][mt],
                          bf[cur][j >> 1][j & 1], bf[cur][j >> 1][(j & 1) + 2]);
        }
    }

    // ---- fused epilogue: d2 = qsq + msq - (2/S^2)*acc, push vs bound ----
    const int g  = lane >> 2;
    const int tg = lane & 3;
    #pragma unroll
    for (int mt = 0; mt < 4; mt++) {
        const int r0 = wm * 64 + mt * 16 + g;
        const size_t gr0 = n0 + r0;
        const size_t gr1 = gr0 + 8;
        const float ms0 = g_msq[gr0];
        const float ms1 = g_msq[gr1];
        #pragma unroll
        for (int j = 0; j < 4; j++) {
            const int ql0 = wn * 32 + j * 8 + 2 * tg;
            const int ql1 = ql0 + 1;
            const int q0 = q0g + ql0, q1 = q0g + ql1;
            const float qs0 = s_qsq[ql0], qs1 = s_qsq[ql1];
            const float b0 = s_bnd[ql0],  b1 = s_bnd[ql1];
            float d;
            d = qs0 + ms0 - INV2S2 * (float)acc[mt][j][0];
            if (d < b0 && gr0 < NM) {
                unsigned pos = atomicAdd(&g_ccnt[q0], 1u);
                if (pos < CAP) { g_cd[(size_t)q0 * CAP + pos] = d; g_ci[(size_t)q0 * CAP + pos] = (int)gr0; }
            }
            d = qs1 + ms0 - INV2S2 * (float)acc[mt][j][1];
            if (d < b1 && gr0 < NM) {
                unsigned pos = atomicAdd(&g_ccnt[q1], 1u);
                if (pos < CAP) { g_cd[(size_t)q1 * CAP + pos] = d; g_ci[(size_t)q1 * CAP + pos] = (int)gr0; }
            }
            d = qs0 + ms1 - INV2S2 * (float)acc[mt][j][2];
            if (d < b0 && gr1 < NM) {
                unsigned pos = atomicAdd(&g_ccnt[q0], 1u);
                if (pos < CAP) { g_cd[(size_t)q0 * CAP + pos] = d; g_ci[(size_t)q0 * CAP + pos] = (int)gr1; }
            }
            d = qs1 + ms1 - INV2S2 * (float)acc[mt][j][3];
            if (d < b1 && gr1 < NM) {
                unsigned pos = atomicAdd(&g_ccnt[q1], 1u);
                if (pos < CAP) { g_cd[(size_t)q1 * CAP + pos] = d; g_ci[(size_t)q1 * CAP + pos] = (int)gr1; }
            }
        }
    }
}

// ---------------- final: approx top-16, exact fp32 rescoring, top-5 ----------------
#define FT 512
__global__ __launch_bounds__(FT)
void final_kernel(const float* __restrict__ query, const float* __restrict__ memory,
                  float* __restrict__ out) {
    const int q = blockIdx.x;
    const int tid = threadIdx.x;
    const int cnt = min((int)g_ccnt[q], CAP);
    const float* cd = g_cd + (size_t)q * CAP;
    const int*   ci = g_ci + (size_t)q * CAP;

    float v[KCAND];
    int   id[KCAND];
    #pragma unroll
    for (int i = 0; i < KCAND; i++) { v[i] = 3.4e38f; id[i] = 0x7fffffff; }

    for (int n = tid; n < cnt; n += FT) {
        float d = cd[n];
        int   ix = ci[n];
        if (d < v[KCAND - 1] || (d == v[KCAND - 1] && ix < id[KCAND - 1])) {
            int pos = KCAND - 1;
            #pragma unroll
            for (int j = KCAND - 2; j >= 0; j--) {
                if (d < v[j] || (d == v[j] && ix < id[j])) {
                    v[j + 1] = v[j]; id[j + 1] = id[j]; pos = j;
                }
            }
            v[pos] = d; id[pos] = ix;
        }
    }

    __shared__ float sval[FT];
    __shared__ int   sidx[FT];
    __shared__ int   cid[KCAND];
    __shared__ float cex[KCAND];
    int p = 0;

    for (int sel = 0; sel < KCAND; sel++) {
        sval[tid] = (p < KCAND) ? v[p] : 3.4e38f;
        sidx[tid] = (p < KCAND) ? id[p] : 0x7fffffff;
        __syncthreads();
        for (int s = FT / 2; s > 0; s >>= 1) {
            if (tid < s) {
                float a = sval[tid], b = sval[tid + s];
                int   ai = sidx[tid], bi = sidx[tid + s];
                if (b < a || (b == a && bi < ai)) { sval[tid] = b; sidx[tid] = bi; }
            }
            __syncthreads();
        }
        int besti = sidx[0];
        __syncthreads();
        if (p < KCAND && id[p] == besti) p++;
        if (tid == 0) cid[sel] = besti;
        __syncthreads();
    }

    // exact fp32 rescoring: one warp per candidate
    const int w = tid >> 5, lane = tid & 31;
    if (w < KCAND) {
        const int cix = cid[w];
        const float4* qr = (const float4*)(query + (size_t)q * DIM);
        const float4* mr = (const float4*)(memory + (size_t)cix * DIM);
        float s = 0.f;
        #pragma unroll
        for (int i = lane; i < DIM / 4; i += 32) {
            float4 a = qr[i], b = mr[i];
            s += a.x * b.x + a.y * b.y + a.z * b.z + a.w * b.w;
        }
        #pragma unroll
        for (int o = 16; o; o >>= 1) s += __shfl_xor_sync(0xffffffff, s, o);
        if (lane == 0) cex[w] = g_qsq[q] + g_msq[cix] - 2.f * s;
    }
    __syncthreads();

    if (tid == 0) {
        float e[KCAND]; int ii[KCAND];
        #pragma unroll
        for (int i = 0; i < KCAND; i++) { e[i] = cex[i]; ii[i] = cid[i]; }
        #pragma unroll
        for (int i = 1; i < KCAND; i++) {
            float ev = e[i]; int iv = ii[i];
            int j = i - 1;
            while (j >= 0 && (e[j] > ev || (e[j] == ev && ii[j] > iv))) {
                e[j + 1] = e[j]; ii[j + 1] = ii[j]; j--;
            }
            e[j + 1] = ev; ii[j + 1] = iv;
        }
        #pragma unroll
        for (int k = 0; k < KSEL; k++) {
            out[q * KSEL + k] = e[k];
            out[BQ * KSEL + q * KSEL + k] = (float)ii[k];
        }
    }
}

// ---------------- launcher ----------------
extern "C" void kernel_launch(void* const* d_in, const int* in_sizes, int n_in,
                              void* d_out, int out_size) {
    const float* query  = (const float*)d_in[0];
    const float* memory = (const float*)d_in[1];
    if (n_in >= 2 && in_sizes[0] != BQ * DIM && in_sizes[1] == BQ * DIM) {
        const float* t = query; query = memory; memory = t;
    }
    float* out = (float*)d_out;

    float* d_msq; cudaGetSymbolAddress((void**)&d_msq, g_msq);
    float* d_qsq; cudaGetSymbolAddress((void**)&d_qsq, g_qsq);
    int8_t* d_mh; cudaGetSymbolAddress((void**)&d_mh, g_mh);
    int8_t* d_qh; cudaGetSymbolAddress((void**)&d_qh, g_qh);

    seed_kernel<<<BQ, 256>>>(query, memory);

    split_kernel<<<(NM * 32 + 255) / 256, 256>>>(memory, d_mh, d_msq, NM);
    split_kernel<<<(BQ * 32 + 255) / 256, 256>>>(query, d_qh, d_qsq, BQ);

    cudaFuncSetAttribute(gemm_kernel, cudaFuncAttributeMaxDynamicSharedMemorySize,
                         SMEM_REQ);
    dim3 grid(BQ / NQT, NTILES);
    gemm_kernel<<<grid, GT, SMEM_REQ>>>();

    final_kernel<<<BQ, FT>>>(query, memory, out);
}

// round 14
// speedup vs baseline: 1.5839x; 1.5839x over previous
#include <cuda_runtime.h>
#include <cuda_bf16.h>
#include <cstdint>

// ---------------- problem constants ----------------
#define BQ    256
#define NM    500000
#define DIM   512
#define KSEL  5
#define KCAND 16

// ---------------- GEMM tiling ----------------
#define MT      64                  // memory rows per CTA
#define NQT     128                 // queries per CTA
#define KC      64
#define GT      256                 // threads per CTA, 8 warps (2 x 4), warp 32x32
#define NCHUNK  (DIM / KC)          // 8
#define NTILES  ((NM + MT - 1) / MT)        // 7813
#define NMP     (NTILES * MT)               // 500032
#define NSTAGE  3
#define STAGE_B 24576               // A 8KB + B 16KB
#define SMEM_REQ (NSTAGE * STAGE_B + 1024)

// ---------------- candidate filtering ----------------
#define SEEDN   1024
#define NBOUND  5                   // bound = exact 5th-smallest of seed set
#define CAP     16384
#define MARGIN  1.0f

// ---------------- device scratch ----------------
__device__ float         g_msq[NMP];
__device__ float         g_qsq[BQ];
__device__ __nv_bfloat16 g_mh[(size_t)NMP * DIM];
__device__ __nv_bfloat16 g_qh[BQ * DIM];
__device__ float         g_bound[BQ];
__device__ unsigned      g_ccnt[BQ];
__device__ float         g_cd[(size_t)BQ * CAP];
__device__ int           g_ci[(size_t)BQ * CAP];

// ---------------- helpers ----------------
__device__ __forceinline__ uint32_t smem_u32(const void* p) {
    uint32_t a;
    asm("{ .reg .u64 t; cvta.to.shared.u64 t, %1; cvt.u32.u64 %0, t; }" : "=r"(a) : "l"(p));
    return a;
}
#define SWZ(o) ((o) ^ (((o) >> 3) & 0x70))
#define CP16(dst, src) \
    asm volatile("cp.async.cg.shared.global [%0], [%1], 16;" :: "r"(dst), "l"(src))
#define LDSM4(r, addr)                                                    \
    asm volatile("ldmatrix.sync.aligned.m8n8.x4.shared.b16 {%0,%1,%2,%3}, [%4];" \
                 : "=r"((r)[0]), "=r"((r)[1]), "=r"((r)[2]), "=r"((r)[3]) \
                 : "r"(addr))
#define MMA16816(d, a, b0, b1)                                            \
    asm volatile("mma.sync.aligned.m16n8k16.row.col.f32.bf16.bf16.f32 "   \
                 "{%0,%1,%2,%3}, {%4,%5,%6,%7}, {%8,%9}, {%0,%1,%2,%3};"  \
                 : "+f"((d)[0]), "+f"((d)[1]), "+f"((d)[2]), "+f"((d)[3]) \
                 : "r"((a)[0]), "r"((a)[1]), "r"((a)[2]), "r"((a)[3]),    \
                   "r"(b0), "r"(b1))

// ---------------- bf16 convert + squared-norm (one warp per row, 16B stores) ----------------
__global__ void split_kernel(const float* __restrict__ x,
                             __nv_bfloat16* __restrict__ hi,
                             float* __restrict__ sq, int rows) {
    int warp = (blockIdx.x * blockDim.x + threadIdx.x) >> 5;
    int lane = threadIdx.x & 31;
    if (warp >= rows) return;
    const float4* r = (const float4*)(x + (size_t)warp * DIM);
    uint4* h4 = (uint4*)(hi + (size_t)warp * DIM);
    float s = 0.f;
    #pragma unroll
    for (int i = lane; i < DIM / 8; i += 32) {
        float4 a = r[2 * i], b = r[2 * i + 1];
        s += a.x * a.x + a.y * a.y + a.z * a.z + a.w * a.w;
        s += b.x * b.x + b.y * b.y + b.z * b.z + b.w * b.w;
        __nv_bfloat162 p0 = __floats2bfloat162_rn(a.x, a.y);
        __nv_bfloat162 p1 = __floats2bfloat162_rn(a.z, a.w);
        __nv_bfloat162 p2 = __floats2bfloat162_rn(b.x, b.y);
        __nv_bfloat162 p3 = __floats2bfloat162_rn(b.z, b.w);
        uint4 o;
        o.x = *(uint32_t*)&p0; o.y = *(uint32_t*)&p1;
        o.z = *(uint32_t*)&p2; o.w = *(uint32_t*)&p3;
        h4[i] = o;
    }
    #pragma unroll
    for (int o = 16; o; o >>= 1) s += __shfl_xor_sync(0xffffffff, s, o);
    if (lane == 0) sq[warp] = s;
}

// ---------------- seed: exact fp32, bound[q] = 5th-smallest of first SEEDN rows + margin ----------------
__global__ __launch_bounds__(256)
void seed_kernel(const float* __restrict__ query, const float* __restrict__ memory) {
    const int q = blockIdx.x;
    const int tid = threadIdx.x;
    __shared__ float4 qs[DIM / 4];
    __shared__ float sd[SEEDN];
    __shared__ float rv[256];
    __shared__ int   ri[256];

    if (tid == 0) g_ccnt[q] = 0;

    for (int i = tid; i < DIM / 4; i += 256)
        qs[i] = ((const float4*)(query + (size_t)q * DIM))[i];
    __syncthreads();

    for (int r = tid; r < SEEDN; r += 256) {
        const float4* m4 = (const float4*)(memory + (size_t)r * DIM);
        float d = 0.f;
        #pragma unroll 8
        for (int i = 0; i < DIM / 4; i++) {
            float4 a = qs[i], b = m4[i];
            float dx = a.x - b.x, dy = a.y - b.y, dz = a.z - b.z, dw = a.w - b.w;
            d += dx * dx + dy * dy + dz * dz + dw * dw;
        }
        sd[r] = d;
    }
    __syncthreads();

    float last = 0.f;
    for (int sel = 0; sel < NBOUND; sel++) {
        float bv = 3.4e38f; int bi = -1;
        #pragma unroll
        for (int k = 0; k < SEEDN / 256; k++) {
            int i = tid + k * 256;
            float v = sd[i];
            if (v < bv) { bv = v; bi = i; }
        }
        rv[tid] = bv; ri[tid] = bi;
        __syncthreads();
        for (int s = 128; s > 0; s >>= 1) {
            if (tid < s) {
                if (rv[tid + s] < rv[tid]) { rv[tid] = rv[tid + s]; ri[tid] = ri[tid + s]; }
            }
            __syncthreads();
        }
        if (tid == 0) { last = rv[0]; sd[ri[0]] = 3.4e38f; }
        __syncthreads();
    }
    if (tid == 0) g_bound[q] = last + MARGIN;
}

// ---------------- bf16 HMMA GEMM with fused candidate push ----------------
// CTA: 64 rows x 128 queries, 256 threads, 8 warps (wm 2 x wn 4), warp 32x32.
// Target 3 CTAs/SM (regs <= 85, smem 3 x 24KB stages).
__global__ __launch_bounds__(GT, 3)
void gemm_kernel() {
    extern __shared__ char dsm[];
    __shared__ float s_qsq[NQT];
    __shared__ float s_bnd[NQT];
    char* alig = (char*)(((uintptr_t)dsm + 1023) & ~(uintptr_t)1023);
    const uint32_t base = smem_u32(alig);

    const int tid  = threadIdx.x;
    const int wid  = tid >> 5;
    const int lane = tid & 31;
    const int wm   = wid >> 2;          // 0..1 : 32-row band
    const int wn   = wid & 3;           // 0..3 : 32-query band
    const size_t n0 = (size_t)blockIdx.y * MT;   // y = row tile
    const int q0g   = blockIdx.x * NQT;          // x = query half (adjacent bids share A in L2)

    if (tid < NQT) { s_qsq[tid] = g_qsq[q0g + tid]; s_bnd[tid] = g_bound[q0g + tid]; }

    float acc[2][4][4];
    #pragma unroll
    for (int mt = 0; mt < 2; mt++)
        #pragma unroll
        for (int j = 0; j < 4; j++)
            #pragma unroll
            for (int e = 0; e < 4; e++) acc[mt][j][e] = 0.f;

    auto load_stage = [&](int kc, int s) {
        const uint32_t aB = base + s * STAGE_B;
        const uint32_t bB = aB + 8192;
        #pragma unroll
        for (int i = 0; i < 2; i++) {           // A: 64 rows x 8 pieces of 16B
            int c = tid + i * GT;
            int row = c >> 3, piece = c & 7;
            const char* src = (const char*)g_mh +
                (((n0 + (size_t)row) * DIM) + (size_t)kc * KC + piece * 8) * 2;
            CP16(aB + SWZ(row * 128 + piece * 16), src);
        }
        #pragma unroll
        for (int i = 0; i < 4; i++) {           // B: 128 rows x 8 pieces of 16B
            int c = tid + i * GT;
            int row = c >> 3, piece = c & 7;
            const char* src = (const char*)g_qh +
                (((size_t)(q0g + row) * DIM) + (size_t)kc * KC + piece * 8) * 2;
            CP16(bB + SWZ(row * 128 + piece * 16), src);
        }
        asm volatile("cp.async.commit_group;" ::: "memory");
    };

    load_stage(0, 0);
    load_stage(1, 1);

    const int arow  = (lane & 15);
    const int ahalf = (lane >> 4) * 16;

    #pragma unroll 1
    for (int kc = 0; kc < NCHUNK; kc++) {
        const int s = kc % NSTAGE;
        if (kc + 2 < NCHUNK) {
            asm volatile("cp.async.wait_group 1;" ::: "memory");
        } else {
            asm volatile("cp.async.wait_group 0;" ::: "memory");
        }
        __syncthreads();
        if (kc + 2 < NCHUNK) load_stage(kc + 2, (kc + 2) % NSTAGE);

        const uint32_t aS = base + s * STAGE_B;
        const uint32_t bS = aS + 8192;

        uint32_t af[2][2][4], bf[2][2][4];
        #pragma unroll
        for (int mt = 0; mt < 2; mt++) {
            int row = wm * 32 + mt * 16 + arow;
            LDSM4(af[0][mt], aS + SWZ(row * 128 + ahalf));
        }
        #pragma unroll
        for (int nt = 0; nt < 2; nt++) {
            int row = wn * 32 + nt * 16 + arow;
            LDSM4(bf[0][nt], bS + SWZ(row * 128 + ahalf));
        }

        #pragma unroll
        for (int kk = 0; kk < 4; kk++) {
            const int cur = kk & 1;
            const int nxt = cur ^ 1;
            if (kk < 3) {
                #pragma unroll
                for (int mt = 0; mt < 2; mt++) {
                    int row = wm * 32 + mt * 16 + arow;
                    LDSM4(af[nxt][mt], aS + SWZ(row * 128 + (kk + 1) * 32 + ahalf));
                }
                #pragma unroll
                for (int nt = 0; nt < 2; nt++) {
                    int row = wn * 32 + nt * 16 + arow;
                    LDSM4(bf[nxt][nt], bS + SWZ(row * 128 + (kk + 1) * 32 + ahalf));
                }
            }
            #pragma unroll
            for (int mt = 0; mt < 2; mt++)
                #pragma unroll
                for (int j = 0; j < 4; j++)
                    MMA16816(acc[mt][j], af[cur][mt],
                             bf[cur][j >> 1][j & 1], bf[cur][j >> 1][(j & 1) + 2]);
        }
    }

    // ---- fused epilogue: compare vs bound, push rare candidates ----
    const int g  = lane >> 2;
    const int tg = lane & 3;
    #pragma unroll
    for (int mt = 0; mt < 2; mt++) {
        const int r0 = wm * 32 + mt * 16 + g;
        const size_t gr0 = n0 + r0;
        const size_t gr1 = gr0 + 8;
        const float ms0 = g_msq[gr0];
        const float ms1 = g_msq[gr1];
        #pragma unroll
        for (int j = 0; j < 4; j++) {
            const int ql0 = wn * 32 + j * 8 + 2 * tg;
            const int ql1 = ql0 + 1;
            const int q0 = q0g + ql0, q1 = q0g + ql1;
            const float qs0 = s_qsq[ql0], qs1 = s_qsq[ql1];
            const float b0 = s_bnd[ql0],  b1 = s_bnd[ql1];
            float d;
            d = qs0 + ms0 - 2.f * acc[mt][j][0];
            if (d < b0 && gr0 < NM) {
                unsigned pos = atomicAdd(&g_ccnt[q0], 1u);
                if (pos < CAP) { g_cd[(size_t)q0 * CAP + pos] = d; g_ci[(size_t)q0 * CAP + pos] = (int)gr0; }
            }
            d = qs1 + ms0 - 2.f * acc[mt][j][1];
            if (d < b1 && gr0 < NM) {
                unsigned pos = atomicAdd(&g_ccnt[q1], 1u);
                if (pos < CAP) { g_cd[(size_t)q1 * CAP + pos] = d; g_ci[(size_t)q1 * CAP + pos] = (int)gr0; }
            }
            d = qs0 + ms1 - 2.f * acc[mt][j][2];
            if (d < b0 && gr1 < NM) {
                unsigned pos = atomicAdd(&g_ccnt[q0], 1u);
                if (pos < CAP) { g_cd[(size_t)q0 * CAP + pos] = d; g_ci[(size_t)q0 * CAP + pos] = (int)gr1; }
            }
            d = qs1 + ms1 - 2.f * acc[mt][j][3];
            if (d < b1 && gr1 < NM) {
                unsigned pos = atomicAdd(&g_ccnt[q1], 1u);
                if (pos < CAP) { g_cd[(size_t)q1 * CAP + pos] = d; g_ci[(size_t)q1 * CAP + pos] = (int)gr1; }
            }
        }
    }
}

// ---------------- final: approx top-16, exact fp32 rescoring, top-5 ----------------
#define FT 512
__global__ __launch_bounds__(FT)
void final_kernel(const float* __restrict__ query, const float* __restrict__ memory,
                  float* __restrict__ out) {
    const int q = blockIdx.x;
    const int tid = threadIdx.x;
    const int cnt = min((int)g_ccnt[q], CAP);
    const float* cd = g_cd + (size_t)q * CAP;
    const int*   ci = g_ci + (size_t)q * CAP;

    float v[KCAND];
    int   id[KCAND];
    #pragma unroll
    for (int i = 0; i < KCAND; i++) { v[i] = 3.4e38f; id[i] = 0x7fffffff; }

    for (int n = tid; n < cnt; n += FT) {
        float d = cd[n];
        int   ix = ci[n];
        if (d < v[KCAND - 1] || (d == v[KCAND - 1] && ix < id[KCAND - 1])) {
            int pos = KCAND - 1;
            #pragma unroll
            for (int j = KCAND - 2; j >= 0; j--) {
                if (d < v[j] || (d == v[j] && ix < id[j])) {
                    v[j + 1] = v[j]; id[j + 1] = id[j]; pos = j;
                }
            }
            v[pos] = d; id[pos] = ix;
        }
    }

    __shared__ float sval[FT];
    __shared__ int   sidx[FT];
    __shared__ int   cid[KCAND];
    __shared__ float cex[KCAND];
    int p = 0;

    for (int sel = 0; sel < KCAND; sel++) {
        sval[tid] = (p < KCAND) ? v[p] : 3.4e38f;
        sidx[tid] = (p < KCAND) ? id[p] : 0x7fffffff;
        __syncthreads();
        for (int s = FT / 2; s > 0; s >>= 1) {
            if (tid < s) {
                float a = sval[tid], b = sval[tid + s];
                int   ai = sidx[tid], bi = sidx[tid + s];
                if (b < a || (b == a && bi < ai)) { sval[tid] = b; sidx[tid] = bi; }
            }
            __syncthreads();
        }
        int besti = sidx[0];
        __syncthreads();
        if (p < KCAND && id[p] == besti) p++;
        if (tid == 0) cid[sel] = besti;
        __syncthreads();
    }

    // exact fp32 rescoring: one warp per candidate
    const int w = tid >> 5, lane = tid & 31;
    if (w < KCAND) {
        const int cix = cid[w];
        const float4* qr = (const float4*)(query + (size_t)q * DIM);
        const float4* mr = (const float4*)(memory + (size_t)cix * DIM);
        float s = 0.f;
        #pragma unroll
        for (int i = lane; i < DIM / 4; i += 32) {
            float4 a = qr[i], b = mr[i];
            s += a.x * b.x + a.y * b.y + a.z * b.z + a.w * b.w;
        }
        #pragma unroll
        for (int o = 16; o; o >>= 1) s += __shfl_xor_sync(0xffffffff, s, o);
        if (lane == 0) cex[w] = g_qsq[q] + g_msq[cix] - 2.f * s;
    }
    __syncthreads();

    if (tid == 0) {
        float e[KCAND]; int ii[KCAND];
        #pragma unroll
        for (int i = 0; i < KCAND; i++) { e[i] = cex[i]; ii[i] = cid[i]; }
        #pragma unroll
        for (int i = 1; i < KCAND; i++) {
            float ev = e[i]; int iv = ii[i];
            int j = i - 1;
            while (j >= 0 && (e[j] > ev || (e[j] == ev && ii[j] > iv))) {
                e[j + 1] = e[j]; ii[j + 1] = ii[j]; j--;
            }
            e[j + 1] = ev; ii[j + 1] = iv;
        }
        #pragma unroll
        for (int k = 0; k < KSEL; k++) {
            out[q * KSEL + k] = e[k];
            out[BQ * KSEL + q * KSEL + k] = (float)ii[k];
        }
    }
}

// ---------------- launcher ----------------
extern "C" void kernel_launch(void* const* d_in, const int* in_sizes, int n_in,
                              void* d_out, int out_size) {
    const float* query  = (const float*)d_in[0];
    const float* memory = (const float*)d_in[1];
    if (n_in >= 2 && in_sizes[0] != BQ * DIM && in_sizes[1] == BQ * DIM) {
        const float* t = query; query = memory; memory = t;
    }
    float* out = (float*)d_out;

    float* d_msq; cudaGetSymbolAddress((void**)&d_msq, g_msq);
    float* d_qsq; cudaGetSymbolAddress((void**)&d_qsq, g_qsq);
    __nv_bfloat16* d_mh; cudaGetSymbolAddress((void**)&d_mh, g_mh);
    __nv_bfloat16* d_qh; cudaGetSymbolAddress((void**)&d_qh, g_qh);

    seed_kernel<<<BQ, 256>>>(query, memory);

    split_kernel<<<(NM * 32 + 255) / 256, 256>>>(memory, d_mh, d_msq, NM);
    split_kernel<<<(BQ * 32 + 255) / 256, 256>>>(query, d_qh, d_qsq, BQ);

    cudaFuncSetAttribute(gemm_kernel, cudaFuncAttributeMaxDynamicSharedMemorySize,
                         SMEM_REQ);
    dim3 grid(BQ / NQT, NTILES);
    gemm_kernel<<<grid, GT, SMEM_REQ>>>();

    final_kernel<<<BQ, FT>>>(query, memory, out);
}

// round 15
// speedup vs baseline: 1.7398x; 1.0984x over previous
#include <cuda_runtime.h>
#include <cuda_bf16.h>
#include <cstdint>

// ---------------- problem constants ----------------
#define BQ    256
#define NM    500000
#define DIM   512
#define KSEL  5
#define KCAND 16

// ---------------- GEMM tiling ----------------
#define MT      64                  // memory rows per CTA
#define NQT     128                 // queries per CTA
#define KC      64
#define GT      256                 // threads per CTA, 8 warps (2 x 4), warp 32x32
#define NCHUNK  (DIM / KC)          // 8
#define NTILES  ((NM + MT - 1) / MT)        // 7813
#define NMP     (NTILES * MT)               // 500032
#define NSTAGE  3
#define STAGE_B 24576               // A 8KB + B 16KB
#define SMEM_REQ (NSTAGE * STAGE_B + 1024)

// ---------------- pipeline chunking ----------------
#define NPIPE   4
#define TPC     ((NTILES + NPIPE - 1) / NPIPE)   // 1954 tiles per chunk

// ---------------- candidate filtering ----------------
#define SEEDN   1024
#define NBOUND  5
#define CAP     16384
#define MARGIN  1.0f

// ---------------- device scratch ----------------
__device__ float         g_msq[NMP];
__device__ float         g_qsq[BQ];
__device__ __nv_bfloat16 g_mh[(size_t)NMP * DIM];
__device__ __nv_bfloat16 g_qh[BQ * DIM];
__device__ float         g_bound[BQ];
__device__ unsigned      g_ccnt[BQ];
__device__ float         g_cd[(size_t)BQ * CAP];
__device__ int           g_ci[(size_t)BQ * CAP];

// ---------------- helpers ----------------
__device__ __forceinline__ uint32_t smem_u32(const void* p) {
    uint32_t a;
    asm("{ .reg .u64 t; cvta.to.shared.u64 t, %1; cvt.u32.u64 %0, t; }" : "=r"(a) : "l"(p));
    return a;
}
#define SWZ(o) ((o) ^ (((o) >> 3) & 0x70))
#define CP16(dst, src) \
    asm volatile("cp.async.cg.shared.global [%0], [%1], 16;" :: "r"(dst), "l"(src))
#define LDSM4(r, addr)                                                    \
    asm volatile("ldmatrix.sync.aligned.m8n8.x4.shared.b16 {%0,%1,%2,%3}, [%4];" \
                 : "=r"((r)[0]), "=r"((r)[1]), "=r"((r)[2]), "=r"((r)[3]) \
                 : "r"(addr))
#define MMA16816(d, a, b0, b1)                                            \
    asm volatile("mma.sync.aligned.m16n8k16.row.col.f32.bf16.bf16.f32 "   \
                 "{%0,%1,%2,%3}, {%4,%5,%6,%7}, {%8,%9}, {%0,%1,%2,%3};"  \
                 : "+f"((d)[0]), "+f"((d)[1]), "+f"((d)[2]), "+f"((d)[3]) \
                 : "r"((a)[0]), "r"((a)[1]), "r"((a)[2]), "r"((a)[3]),    \
                   "r"(b0), "r"(b1))

// ---------------- bf16 convert + squared-norm (row range [r0, r1)) ----------------
__global__ void split_kernel(const float* __restrict__ x,
                             __nv_bfloat16* __restrict__ hi,
                             float* __restrict__ sq, int r0, int r1) {
    int warp = r0 + ((blockIdx.x * blockDim.x + threadIdx.x) >> 5);
    int lane = threadIdx.x & 31;
    if (warp >= r1) return;
    const float4* r = (const float4*)(x + (size_t)warp * DIM);
    uint4* h4 = (uint4*)(hi + (size_t)warp * DIM);
    float s = 0.f;
    #pragma unroll
    for (int i = lane; i < DIM / 8; i += 32) {
        float4 a = r[2 * i], b = r[2 * i + 1];
        s += a.x * a.x + a.y * a.y + a.z * a.z + a.w * a.w;
        s += b.x * b.x + b.y * b.y + b.z * b.z + b.w * b.w;
        __nv_bfloat162 p0 = __floats2bfloat162_rn(a.x, a.y);
        __nv_bfloat162 p1 = __floats2bfloat162_rn(a.z, a.w);
        __nv_bfloat162 p2 = __floats2bfloat162_rn(b.x, b.y);
        __nv_bfloat162 p3 = __floats2bfloat162_rn(b.z, b.w);
        uint4 o;
        o.x = *(uint32_t*)&p0; o.y = *(uint32_t*)&p1;
        o.z = *(uint32_t*)&p2; o.w = *(uint32_t*)&p3;
        h4[i] = o;
    }
    #pragma unroll
    for (int o = 16; o; o >>= 1) s += __shfl_xor_sync(0xffffffff, s, o);
    if (lane == 0) sq[warp] = s;
}

// ---------------- seed: exact fp32, bound[q] = 5th-smallest of first SEEDN rows + margin ----------------
__global__ __launch_bounds__(256)
void seed_kernel(const float* __restrict__ query, const float* __restrict__ memory) {
    const int q = blockIdx.x;
    const int tid = threadIdx.x;
    __shared__ float4 qs[DIM / 4];
    __shared__ float sd[SEEDN];
    __shared__ float rv[256];
    __shared__ int   ri[256];

    if (tid == 0) g_ccnt[q] = 0;

    for (int i = tid; i < DIM / 4; i += 256)
        qs[i] = ((const float4*)(query + (size_t)q * DIM))[i];
    __syncthreads();

    for (int r = tid; r < SEEDN; r += 256) {
        const float4* m4 = (const float4*)(memory + (size_t)r * DIM);
        float d = 0.f;
        #pragma unroll 8
        for (int i = 0; i < DIM / 4; i++) {
            float4 a = qs[i], b = m4[i];
            float dx = a.x - b.x, dy = a.y - b.y, dz = a.z - b.z, dw = a.w - b.w;
            d += dx * dx + dy * dy + dz * dz + dw * dw;
        }
        sd[r] = d;
    }
    __syncthreads();

    float last = 0.f;
    for (int sel = 0; sel < NBOUND; sel++) {
        float bv = 3.4e38f; int bi = -1;
        #pragma unroll
        for (int k = 0; k < SEEDN / 256; k++) {
            int i = tid + k * 256;
            float v = sd[i];
            if (v < bv) { bv = v; bi = i; }
        }
        rv[tid] = bv; ri[tid] = bi;
        __syncthreads();
        for (int s = 128; s > 0; s >>= 1) {
            if (tid < s) {
                if (rv[tid + s] < rv[tid]) { rv[tid] = rv[tid + s]; ri[tid] = ri[tid + s]; }
            }
            __syncthreads();
        }
        if (tid == 0) { last = rv[0]; sd[ri[0]] = 3.4e38f; }
        __syncthreads();
    }
    if (tid == 0) g_bound[q] = last + MARGIN;
}

// ---------------- bf16 HMMA GEMM with fused candidate push ----------------
__global__ __launch_bounds__(GT, 3)
void gemm_kernel(int tile0) {
    extern __shared__ char dsm[];
    __shared__ float s_qsq[NQT];
    __shared__ float s_bnd[NQT];
    char* alig = (char*)(((uintptr_t)dsm + 1023) & ~(uintptr_t)1023);
    const uint32_t base = smem_u32(alig);

    const int tid  = threadIdx.x;
    const int wid  = tid >> 5;
    const int lane = tid & 31;
    const int wm   = wid >> 2;
    const int wn   = wid & 3;
    const size_t n0 = (size_t)(tile0 + blockIdx.y) * MT;
    const int q0g   = blockIdx.x * NQT;

    if (tid < NQT) { s_qsq[tid] = g_qsq[q0g + tid]; s_bnd[tid] = g_bound[q0g + tid]; }

    float acc[2][4][4];
    #pragma unroll
    for (int mt = 0; mt < 2; mt++)
        #pragma unroll
        for (int j = 0; j < 4; j++)
            #pragma unroll
            for (int e = 0; e < 4; e++) acc[mt][j][e] = 0.f;

    auto load_stage = [&](int kc, int s) {
        const uint32_t aB = base + s * STAGE_B;
        const uint32_t bB = aB + 8192;
        #pragma unroll
        for (int i = 0; i < 2; i++) {
            int c = tid + i * GT;
            int row = c >> 3, piece = c & 7;
            const char* src = (const char*)g_mh +
                (((n0 + (size_t)row) * DIM) + (size_t)kc * KC + piece * 8) * 2;
            CP16(aB + SWZ(row * 128 + piece * 16), src);
        }
        #pragma unroll
        for (int i = 0; i < 4; i++) {
            int c = tid + i * GT;
            int row = c >> 3, piece = c & 7;
            const char* src = (const char*)g_qh +
                (((size_t)(q0g + row) * DIM) + (size_t)kc * KC + piece * 8) * 2;
            CP16(bB + SWZ(row * 128 + piece * 16), src);
        }
        asm volatile("cp.async.commit_group;" ::: "memory");
    };

    load_stage(0, 0);
    load_stage(1, 1);

    const int arow  = (lane & 15);
    const int ahalf = (lane >> 4) * 16;

    #pragma unroll 1
    for (int kc = 0; kc < NCHUNK; kc++) {
        const int s = kc % NSTAGE;
        if (kc + 2 < NCHUNK) {
            asm volatile("cp.async.wait_group 1;" ::: "memory");
        } else {
            asm volatile("cp.async.wait_group 0;" ::: "memory");
        }
        __syncthreads();
        if (kc + 2 < NCHUNK) load_stage(kc + 2, (kc + 2) % NSTAGE);

        const uint32_t aS = base + s * STAGE_B;
        const uint32_t bS = aS + 8192;

        uint32_t af[2][2][4], bf[2][2][4];
        #pragma unroll
        for (int mt = 0; mt < 2; mt++) {
            int row = wm * 32 + mt * 16 + arow;
            LDSM4(af[0][mt], aS + SWZ(row * 128 + ahalf));
        }
        #pragma unroll
        for (int nt = 0; nt < 2; nt++) {
            int row = wn * 32 + nt * 16 + arow;
            LDSM4(bf[0][nt], bS + SWZ(row * 128 + ahalf));
        }

        #pragma unroll
        for (int kk = 0; kk < 4; kk++) {
            const int cur = kk & 1;
            const int nxt = cur ^ 1;
            if (kk < 3) {
                #pragma unroll
                for (int mt = 0; mt < 2; mt++) {
                    int row = wm * 32 + mt * 16 + arow;
                    LDSM4(af[nxt][mt], aS + SWZ(row * 128 + (kk + 1) * 32 + ahalf));
                }
                #pragma unroll
                for (int nt = 0; nt < 2; nt++) {
                    int row = wn * 32 + nt * 16 + arow;
                    LDSM4(bf[nxt][nt], bS + SWZ(row * 128 + (kk + 1) * 32 + ahalf));
                }
            }
            #pragma unroll
            for (int mt = 0; mt < 2; mt++)
                #pragma unroll
                for (int j = 0; j < 4; j++)
                    MMA16816(acc[mt][j], af[cur][mt],
                             bf[cur][j >> 1][j & 1], bf[cur][j >> 1][(j & 1) + 2]);
        }
    }

    // ---- fused epilogue: compare vs bound, push rare candidates ----
    const int g  = lane >> 2;
    const int tg = lane & 3;
    #pragma unroll
    for (int mt = 0; mt < 2; mt++) {
        const int r0 = wm * 32 + mt * 16 + g;
        const size_t gr0 = n0 + r0;
        const size_t gr1 = gr0 + 8;
        const float ms0 = g_msq[gr0];
        const float ms1 = g_msq[gr1];
        #pragma unroll
        for (int j = 0; j < 4; j++) {
            const int ql0 = wn * 32 + j * 8 + 2 * tg;
            const int ql1 = ql0 + 1;
            const int q0 = q0g + ql0, q1 = q0g + ql1;
            const float qs0 = s_qsq[ql0], qs1 = s_qsq[ql1];
            const float b0 = s_bnd[ql0],  b1 = s_bnd[ql1];
            float d;
            d = qs0 + ms0 - 2.f * acc[mt][j][0];
            if (d < b0 && gr0 < NM) {
                unsigned pos = atomicAdd(&g_ccnt[q0], 1u);
                if (pos < CAP) { g_cd[(size_t)q0 * CAP + pos] = d; g_ci[(size_t)q0 * CAP + pos] = (int)gr0; }
            }
            d = qs1 + ms0 - 2.f * acc[mt][j][1];
            if (d < b1 && gr0 < NM) {
                unsigned pos = atomicAdd(&g_ccnt[q1], 1u);
                if (pos < CAP) { g_cd[(size_t)q1 * CAP + pos] = d; g_ci[(size_t)q1 * CAP + pos] = (int)gr0; }
            }
            d = qs0 + ms1 - 2.f * acc[mt][j][2];
            if (d < b0 && gr1 < NM) {
                unsigned pos = atomicAdd(&g_ccnt[q0], 1u);
                if (pos < CAP) { g_cd[(size_t)q0 * CAP + pos] = d; g_ci[(size_t)q0 * CAP + pos] = (int)gr1; }
            }
            d = qs1 + ms1 - 2.f * acc[mt][j][3];
            if (d < b1 && gr1 < NM) {
                unsigned pos = atomicAdd(&g_ccnt[q1], 1u);
                if (pos < CAP) { g_cd[(size_t)q1 * CAP + pos] = d; g_ci[(size_t)q1 * CAP + pos] = (int)gr1; }
            }
        }
    }
}

// ---------------- final: approx top-16, exact fp32 rescoring, top-5 ----------------
#define FT 512
__global__ __launch_bounds__(FT)
void final_kernel(const float* __restrict__ query, const float* __restrict__ memory,
                  float* __restrict__ out) {
    const int q = blockIdx.x;
    const int tid = threadIdx.x;
    const int cnt = min((int)g_ccnt[q], CAP);
    const float* cd = g_cd + (size_t)q * CAP;
    const int*   ci = g_ci + (size_t)q * CAP;

    float v[KCAND];
    int   id[KCAND];
    #pragma unroll
    for (int i = 0; i < KCAND; i++) { v[i] = 3.4e38f; id[i] = 0x7fffffff; }

    for (int n = tid; n < cnt; n += FT) {
        float d = cd[n];
        int   ix = ci[n];
        if (d < v[KCAND - 1] || (d == v[KCAND - 1] && ix < id[KCAND - 1])) {
            int pos = KCAND - 1;
            #pragma unroll
            for (int j = KCAND - 2; j >= 0; j--) {
                if (d < v[j] || (d == v[j] && ix < id[j])) {
                    v[j + 1] = v[j]; id[j + 1] = id[j]; pos = j;
                }
            }
            v[pos] = d; id[pos] = ix;
        }
    }

    __shared__ float sval[FT];
    __shared__ int   sidx[FT];
    __shared__ int   cid[KCAND];
    __shared__ float cex[KCAND];
    int p = 0;

    for (int sel = 0; sel < KCAND; sel++) {
        sval[tid] = (p < KCAND) ? v[p] : 3.4e38f;
        sidx[tid] = (p < KCAND) ? id[p] : 0x7fffffff;
        __syncthreads();
        for (int s = FT / 2; s > 0; s >>= 1) {
            if (tid < s) {
                float a = sval[tid], b = sval[tid + s];
                int   ai = sidx[tid], bi = sidx[tid + s];
                if (b < a || (b == a && bi < ai)) { sval[tid] = b; sidx[tid] = bi; }
            }
            __syncthreads();
        }
        int besti = sidx[0];
        __syncthreads();
        if (p < KCAND && id[p] == besti) p++;
        if (tid == 0) cid[sel] = besti;
        __syncthreads();
    }

    const int w = tid >> 5, lane = tid & 31;
    if (w < KCAND) {
        const int cix = cid[w];
        const float4* qr = (const float4*)(query + (size_t)q * DIM);
        const float4* mr = (const float4*)(memory + (size_t)cix * DIM);
        float s = 0.f;
        #pragma unroll
        for (int i = lane; i < DIM / 4; i += 32) {
            float4 a = qr[i], b = mr[i];
            s += a.x * b.x + a.y * b.y + a.z * b.z + a.w * b.w;
        }
        #pragma unroll
        for (int o = 16; o; o >>= 1) s += __shfl_xor_sync(0xffffffff, s, o);
        if (lane == 0) cex[w] = g_qsq[q] + g_msq[cix] - 2.f * s;
    }
    __syncthreads();

    if (tid == 0) {
        float e[KCAND]; int ii[KCAND];
        #pragma unroll
        for (int i = 0; i < KCAND; i++) { e[i] = cex[i]; ii[i] = cid[i]; }
        #pragma unroll
        for (int i = 1; i < KCAND; i++) {
            float ev = e[i]; int iv = ii[i];
            int j = i - 1;
            while (j >= 0 && (e[j] > ev || (e[j] == ev && ii[j] > iv))) {
                e[j + 1] = e[j]; ii[j + 1] = ii[j]; j--;
            }
            e[j + 1] = ev; ii[j + 1] = iv;
        }
        #pragma unroll
        for (int k = 0; k < KSEL; k++) {
            out[q * KSEL + k] = e[k];
            out[BQ * KSEL + q * KSEL + k] = (float)ii[k];
        }
    }
}

// ---------------- launcher: 2-stream software pipeline (graph-capturable fork/join) ----------------
extern "C" void kernel_launch(void* const* d_in, const int* in_sizes, int n_in,
                              void* d_out, int out_size) {
    const float* query  = (const float*)d_in[0];
    const float* memory = (const float*)d_in[1];
    if (n_in >= 2 && in_sizes[0] != BQ * DIM && in_sizes[1] == BQ * DIM) {
        const float* t = query; query = memory; memory = t;
    }
    float* out = (float*)d_out;

    float* d_msq; cudaGetSymbolAddress((void**)&d_msq, g_msq);
    float* d_qsq; cudaGetSymbolAddress((void**)&d_qsq, g_qsq);
    __nv_bfloat16* d_mh; cudaGetSymbolAddress((void**)&d_mh, g_mh);
    __nv_bfloat16* d_qh; cudaGetSymbolAddress((void**)&d_qh, g_qh);

    static cudaStream_t s1 = nullptr;
    static cudaEvent_t evFork = nullptr, evChunk[NPIPE], evJoin = nullptr;
    if (!s1) {
        cudaStreamCreateWithFlags(&s1, cudaStreamNonBlocking);
        cudaEventCreateWithFlags(&evFork, cudaEventDisableTiming);
        for (int c = 0; c < NPIPE; c++)
            cudaEventCreateWithFlags(&evChunk[c], cudaEventDisableTiming);
        cudaEventCreateWithFlags(&evJoin, cudaEventDisableTiming);
        cudaFuncSetAttribute(gemm_kernel, cudaFuncAttributeMaxDynamicSharedMemorySize,
                             SMEM_REQ);
    }

    // fork: s1 runs seed (independent of split)
    cudaEventRecord(evFork, 0);
    cudaStreamWaitEvent(s1, evFork, 0);
    seed_kernel<<<BQ, 256, 0, s1>>>(query, memory);

    // stream 0: query split, then memory split in NPIPE row chunks
    split_kernel<<<(BQ * 32 + 255) / 256, 256>>>(query, d_qh, d_qsq, 0, BQ);
    for (int c = 0; c < NPIPE; c++) {
        int t0 = c * TPC;
        int t1 = min(NTILES, t0 + TPC);
        int r0 = t0 * MT;
        int r1 = min(NM, t1 * MT);
        int nwarp = r1 - r0;
        split_kernel<<<(nwarp * 32 + 255) / 256, 256>>>(memory, d_mh, d_msq, r0, r1);
        cudaEventRecord(evChunk[c], 0);
    }

    // s1: per-chunk GEMM as soon as its split lands (seed already ordered before)
    for (int c = 0; c < NPIPE; c++) {
        int t0 = c * TPC;
        int t1 = min(NTILES, t0 + TPC);
        cudaStreamWaitEvent(s1, evChunk[c], 0);
        dim3 grid(BQ / NQT, t1 - t0);
        gemm_kernel<<<grid, GT, SMEM_REQ, s1>>>(t0);
    }

    // join: final on stream 0 after all GEMM chunks
    cudaEventRecord(evJoin, s1);
    cudaStreamWaitEvent(0, evJoin, 0);
    final_kernel<<<BQ, FT>>>(query, memory, out);
}